// round 16
// baseline (speedup 1.0000x reference)
#include <cuda_runtime.h>
#include <cuda_bf16.h>
#include <cstdint>

#define NN   50000
#define EE   640000
#define HIDD 128
#define NT   256   // 8 warps per GEMM CTA, 2 CTAs/SM

// ---------------- device scratch ----------------
__device__ float         g_ft[NN * HIDD];
__device__ __nv_bfloat16 g_kh[NN * HIDD];
__device__ __nv_bfloat16 g_qh[NN * HIDD];
__device__ float4        g_wbf[8 * 4096];   // 8 matrices x (32KB hi + 32KB lo), swizzled
__device__ int   g_cnt[NN];
__device__ int   g_off[NN + 1];
__device__ int   g_cur[NN];
__device__ int   g_eid[EE];
__device__ int   g_esrc[EE];
__device__ int   g_bsum[256];
__device__ int   g_boff[256];

// ---------------- warp-mma helpers ----------------
__device__ __forceinline__ uint32_t smem_u32(const void* p)
{
    uint32_t a;
    asm("{ .reg .u64 t; cvta.to.shared.u64 t, %1; cvt.u32.u64 %0, t; }" : "=r"(a) : "l"(p));
    return a;
}
__device__ __forceinline__ void ldsm4(uint32_t& r0, uint32_t& r1, uint32_t& r2, uint32_t& r3,
                                      uint32_t addr)
{
    asm volatile("ldmatrix.sync.aligned.m8n8.x4.shared.b16 {%0,%1,%2,%3}, [%4];"
                 : "=r"(r0), "=r"(r1), "=r"(r2), "=r"(r3) : "r"(addr));
}
__device__ __forceinline__ void mma16816(float* c, const uint32_t* a, uint32_t b0, uint32_t b1)
{
    asm volatile(
        "mma.sync.aligned.m16n8k16.row.col.f32.bf16.bf16.f32 "
        "{%0,%1,%2,%3}, {%4,%5,%6,%7}, {%8,%9}, {%0,%1,%2,%3};"
        : "+f"(c[0]), "+f"(c[1]), "+f"(c[2]), "+f"(c[3])
        : "r"(a[0]), "r"(a[1]), "r"(a[2]), "r"(a[3]), "r"(b0), "r"(b1));
}

#define CP_COMMIT() asm volatile("cp.async.commit_group;" ::: "memory")
#define CP_WAIT(n)  asm volatile("cp.async.wait_group %0;" :: "n"(n) : "memory")

__device__ __forceinline__ uint32_t sw(int r, int u)
{
    return (uint32_t)(r * 256 + ((u ^ (r & 7)) << 4));
}

// SMEM: X hi/lo (64 rows, 32KB) + two 32KB W half-buffers = 96KB -> 2 CTAs/SM
#define XH_OFF  0
#define XL_OFF  16384
#define WA_OFF  32768
#define WB_OFF  65536
#define SMEM_GEMM 98304

__device__ __forceinline__ void split_store(char* base, int hi_off, int lo_off,
                                            int r, int u, const float* f)
{
    __nv_bfloat162 hi[4], lo[4];
#pragma unroll
    for (int p = 0; p < 4; p++) {
        __nv_bfloat16 h0 = __float2bfloat16(f[p * 2]);
        __nv_bfloat16 h1 = __float2bfloat16(f[p * 2 + 1]);
        hi[p] = __nv_bfloat162(h0, h1);
        lo[p] = __nv_bfloat162(__float2bfloat16(f[p * 2] - __bfloat162float(h0)),
                               __float2bfloat16(f[p * 2 + 1] - __bfloat162float(h1)));
    }
    uint32_t o = sw(r, u);
    *(uint4*)(base + hi_off + o) = *(uint4*)hi;
    *(uint4*)(base + lo_off + o) = *(uint4*)lo;
}

// stage 64 rows of X
__device__ __forceinline__ void stage_X(char* smem, const float* src, int row0, int n, int tid)
{
#pragma unroll
    for (int j = 0; j < 4; j++) {
        int i = tid + NT * j;
        int r = i >> 4, u = i & 15;
        int gr = row0 + r;
        float4 f0 = make_float4(0.f, 0.f, 0.f, 0.f), f1 = f0;
        if (gr < n) {
            f0 = ((const float4*)(src + (size_t)gr * HIDD))[u * 2];
            f1 = ((const float4*)(src + (size_t)gr * HIDD))[u * 2 + 1];
        }
        float f[8] = {f0.x, f0.y, f0.z, f0.w, f1.x, f1.y, f1.z, f1.w};
        split_store(smem, XH_OFF, XL_OFF, r, u, f);
    }
}

// async copy of a 32KB weight half-block into a smem half-buffer
__device__ __forceinline__ void cpasync_W32(uint32_t sb_dst, const char* gsrc, int tid)
{
#pragma unroll
    for (int j = 0; j < 8; j++) {
        int i = tid + NT * j;
        asm volatile("cp.async.cg.shared.global [%0], [%1], 16;"
                     :: "r"(sb_dst + i * 16), "l"(gsrc + (size_t)i * 16) : "memory");
    }
}

// passes 0+1: acc = Xh*Wh + Xl*Wh  (zeroes acc)
__device__ __forceinline__ void mma_pass01(uint32_t sb, uint32_t woff,
                                           int wid, int lane, float acc[8][4])
{
    int m0 = (wid >> 1) * 16;
    int n0 = (wid & 1) * 64;
    int sel = lane >> 3, lr = lane & 7;
    int us = sel >> 1;
    int ra = (sel & 1) * 8 + lr;

#pragma unroll
    for (int a = 0; a < 8; a++)
#pragma unroll
        for (int p = 0; p < 4; p++) acc[a][p] = 0.f;

    int arow = m0 + ra;
    int brow[4];
#pragma unroll
    for (int j = 0; j < 4; j++) brow[j] = n0 + j * 16 + ra;

#pragma unroll
    for (int k = 0; k < 8; k++) {
        int u = 2 * k + us;
        uint32_t ah[4], al[4], bb[4][4];
        {
            uint32_t o = sw(arow, u);
            ldsm4(ah[0], ah[1], ah[2], ah[3], sb + XH_OFF + o);
            ldsm4(al[0], al[1], al[2], al[3], sb + XL_OFF + o);
        }
#pragma unroll
        for (int j = 0; j < 4; j++) {
            uint32_t o = sw(brow[j], u);
            ldsm4(bb[j][0], bb[j][1], bb[j][2], bb[j][3], sb + woff + o);
        }
#pragma unroll
        for (int j = 0; j < 4; j++)
#pragma unroll
            for (int p = 0; p < 2; p++)
                mma16816(acc[2 * j + p], ah, bb[j][p], bb[j][p + 2]);
#pragma unroll
        for (int j = 0; j < 4; j++)
#pragma unroll
            for (int p = 0; p < 2; p++)
                mma16816(acc[2 * j + p], al, bb[j][p], bb[j][p + 2]);
    }
}

// pass 2: acc += Xh*Wl
__device__ __forceinline__ void mma_pass2(uint32_t sb, uint32_t woff,
                                          int wid, int lane, float acc[8][4])
{
    int m0 = (wid >> 1) * 16;
    int n0 = (wid & 1) * 64;
    int sel = lane >> 3, lr = lane & 7;
    int us = sel >> 1;
    int ra = (sel & 1) * 8 + lr;

    int arow = m0 + ra;
    int brow[4];
#pragma unroll
    for (int j = 0; j < 4; j++) brow[j] = n0 + j * 16 + ra;

#pragma unroll
    for (int k = 0; k < 8; k++) {
        int u = 2 * k + us;
        uint32_t ah[4], bb[4][4];
        {
            uint32_t o = sw(arow, u);
            ldsm4(ah[0], ah[1], ah[2], ah[3], sb + XH_OFF + o);
        }
#pragma unroll
        for (int j = 0; j < 4; j++) {
            uint32_t o = sw(brow[j], u);
            ldsm4(bb[j][0], bb[j][1], bb[j][2], bb[j][3], sb + woff + o);
        }
#pragma unroll
        for (int j = 0; j < 4; j++)
#pragma unroll
            for (int p = 0; p < 2; p++)
                mma16816(acc[2 * j + p], ah, bb[j][p], bb[j][p + 2]);
    }
}

// =============== weight pre-conversion: fp32 -> swizzled bf16 hi/lo ===============
__global__ __launch_bounds__(256) void wprep(
    const float* w0, const float* w1, const float* w2, const float* w3,
    const float* w4, const float* w5, const float* w6, const float* w7)
{
    const float* W;
    switch (blockIdx.x) {
        case 0: W = w0; break; case 1: W = w1; break;
        case 2: W = w2; break; case 3: W = w3; break;
        case 4: W = w4; break; case 5: W = w5; break;
        case 6: W = w6; break; default: W = w7; break;
    }
    char* dst = (char*)g_wbf + (size_t)blockIdx.x * 65536;
    int tid = threadIdx.x;
#pragma unroll
    for (int j = 0; j < 8; j++) {
        int i = tid + 256 * j;
        int r = i >> 4, u = i & 15;
        float4 f0 = ((const float4*)(W + (size_t)r * HIDD))[u * 2];
        float4 f1 = ((const float4*)(W + (size_t)r * HIDD))[u * 2 + 1];
        float f[8] = {f0.x, f0.y, f0.z, f0.w, f1.x, f1.y, f1.z, f1.w};
        split_store(dst, 0, 32768, r, u, f);
    }
}

// =============== fused k+q projection -> bf16 K/Q (split-K pipelined W) ===============
__global__ __launch_bounds__(NT, 2) void proj_kq(
    const float* __restrict__ atom,
    const float* __restrict__ k_b, const float* __restrict__ q_b, int n)
{
    extern __shared__ char smem[];
    uint32_t sb = smem_u32(smem);
    int tid = threadIdx.x, wid = tid >> 5, lane = tid & 31;
    int row0 = blockIdx.x * 64;
    int m0 = (wid >> 1) * 16;
    int n0 = (wid & 1) * 64;

    const char* gw = (const char*)g_wbf;
    cpasync_W32(sb + WA_OFF, gw, tid);          CP_COMMIT();   // G0: WHk -> A
    cpasync_W32(sb + WB_OFF, gw + 32768, tid);  CP_COMMIT();   // G1: WLk -> B
    stage_X(smem, atom, row0, n, tid);

    float acc[8][4];

    // ---- k ----
    CP_WAIT(1); __syncthreads();                 // WHk + X visible
    mma_pass01(sb, WA_OFF, wid, lane, acc);
    __syncthreads();                             // A free
    cpasync_W32(sb + WA_OFF, gw + 65536, tid); CP_COMMIT();   // G2: WHq -> A
    CP_WAIT(1); __syncthreads();                 // WLk visible
    mma_pass2(sb, WB_OFF, wid, lane, acc);
    __syncthreads();                             // B free
    cpasync_W32(sb + WB_OFF, gw + 65536 + 32768, tid); CP_COMMIT();   // G3: WLq -> B
    {
        int rbase = row0 + m0 + (lane >> 2);
#pragma unroll
        for (int a = 0; a < 8; a++) {
            int col = n0 + a * 8 + (lane & 3) * 2;
            float2 bv = *(const float2*)(k_b + col);
#pragma unroll
            for (int h = 0; h < 2; h++) {
                int row = rbase + h * 8;
                if (row >= n) continue;
                *(__nv_bfloat162*)(&g_kh[(size_t)row * HIDD + col]) =
                    __nv_bfloat162(__float2bfloat16(acc[a][h * 2] + bv.x),
                                   __float2bfloat16(acc[a][h * 2 + 1] + bv.y));
            }
        }
    }
    // ---- q ----
    CP_WAIT(1); __syncthreads();                 // WHq visible
    mma_pass01(sb, WA_OFF, wid, lane, acc);
    CP_WAIT(0); __syncthreads();                 // WLq visible
    mma_pass2(sb, WB_OFF, wid, lane, acc);
    {
        int rbase = row0 + m0 + (lane >> 2);
#pragma unroll
        for (int a = 0; a < 8; a++) {
            int col = n0 + a * 8 + (lane & 3) * 2;
            float2 bv = *(const float2*)(q_b + col);
#pragma unroll
            for (int h = 0; h < 2; h++) {
                int row = rbase + h * 8;
                if (row >= n) continue;
                *(__nv_bfloat162*)(&g_qh[(size_t)row * HIDD + col]) =
                    __nv_bfloat162(__float2bfloat16(acc[a][h * 2] + bv.x),
                                   __float2bfloat16(acc[a][h * 2 + 1] + bv.y));
            }
        }
    }
}

// =============== fused 6-layer MLP: split-K pipelined W, reg carry ===============
__global__ __launch_bounds__(NT, 2) void mlp6(
    const float* __restrict__ FT, const float* __restrict__ atom,
    const float* __restrict__ l1b, const float* __restrict__ l2b,
    const float* __restrict__ r1ab, const float* __restrict__ r1bb,
    const float* __restrict__ r2ab, const float* __restrict__ r2bb,
    float* __restrict__ out, int n)
{
    extern __shared__ char smem[];
    uint32_t sb = smem_u32(smem);
    int tid = threadIdx.x, wid = tid >> 5, lane = tid & 31;
    int row0 = blockIdx.x * 64;
    int m0 = (wid >> 1) * 16;
    int n0 = (wid & 1) * 64;

    const float* Bs[6] = {l1b, l2b, r1ab, r1bb, r2ab, r2bb};
    const int reluF[6] = {1, 0, 1, 1, 1, 1};
    const int resF[6]  = {0, 1, 0, 2, 0, 2};   // 0 none, 1 atom, 2 reg-carry
    const int outF[6]  = {0, 1, 0, 1, 0, 2};   // 0 X, 1 X + save carry, 2 out

    const char* gw = (const char*)g_wbf;
    // weight matrices 2..7 = l1,l2,r1a,r1b,r2a,r2b
    cpasync_W32(sb + WA_OFF, gw + (size_t)2 * 65536, tid);         CP_COMMIT(); // WH l1
    cpasync_W32(sb + WB_OFF, gw + (size_t)2 * 65536 + 32768, tid); CP_COMMIT(); // WL l1
    stage_X(smem, FT, row0, n, tid);

    float acc[8][4];
    float car[8][4];

#pragma unroll
    for (int L = 0; L < 6; L++) {
        CP_WAIT(1); __syncthreads();             // WH_L + X visible
        mma_pass01(sb, WA_OFF, wid, lane, acc);
        __syncthreads();                         // A free
        if (L < 5) {
            cpasync_W32(sb + WA_OFF, gw + (size_t)(3 + L) * 65536, tid);
            CP_COMMIT();                         // WH_{L+1} -> A (overlaps pass2)
        }
        if (L < 5) { CP_WAIT(1); } else { CP_WAIT(0); }
        __syncthreads();                         // WL_L visible
        mma_pass2(sb, WB_OFF, wid, lane, acc);

        // finalize values in acc
        int rbase = row0 + m0 + (lane >> 2);
#pragma unroll
        for (int a = 0; a < 8; a++) {
            int col = n0 + a * 8 + (lane & 3) * 2;
            float2 bv = *(const float2*)(Bs[L] + col);
#pragma unroll
            for (int h = 0; h < 2; h++) {
                int row = rbase + h * 8;
                float vx = acc[a][h * 2]     + bv.x;
                float vy = acc[a][h * 2 + 1] + bv.y;
                if (reluF[L]) { vx = fmaxf(vx, 0.f); vy = fmaxf(vy, 0.f); }
                if (resF[L] == 1) {
                    if (row < n) {
                        float2 rv = *(const float2*)(atom + (size_t)row * HIDD + col);
                        vx += rv.x; vy += rv.y;
                    }
                } else if (resF[L] == 2) {
                    vx += car[a][h * 2];
                    vy += car[a][h * 2 + 1];
                }
                acc[a][h * 2]     = vx;
                acc[a][h * 2 + 1] = vy;
                if (outF[L] == 1) {
                    car[a][h * 2]     = vx;
                    car[a][h * 2 + 1] = vy;
                }
            }
        }
        __syncthreads();                         // B free, X free

        if (L < 5) {
            cpasync_W32(sb + WB_OFF, gw + (size_t)(3 + L) * 65536 + 32768, tid);
            CP_COMMIT();                         // WL_{L+1} -> B (overlaps write phase)
        }

        // write phase
        int rl0 = m0 + (lane >> 2);
#pragma unroll
        for (int a = 0; a < 8; a++) {
            int col = n0 + a * 8 + (lane & 3) * 2;
            int u = col >> 3;
#pragma unroll
            for (int h = 0; h < 2; h++) {
                int lr = rl0 + h * 8;
                float vx = acc[a][h * 2], vy = acc[a][h * 2 + 1];
                if (outF[L] == 2) {
                    int row = row0 + lr;
                    if (row < n)
                        *(float2*)(out + (size_t)row * HIDD + col) = make_float2(vx, vy);
                } else {
                    __nv_bfloat16 hx = __float2bfloat16(vx);
                    __nv_bfloat16 hy = __float2bfloat16(vy);
                    uint32_t o = sw(lr, u) + ((col & 7) << 1);
                    *(__nv_bfloat162*)(smem + XH_OFF + o) = __nv_bfloat162(hx, hy);
                    *(__nv_bfloat162*)(smem + XL_OFF + o) =
                        __nv_bfloat162(__float2bfloat16(vx - __bfloat162float(hx)),
                                       __float2bfloat16(vy - __bfloat162float(hy)));
                }
            }
        }
        // next iteration's CP_WAIT + __syncthreads publishes X writes
    }
}

// ---------------- CSR build ----------------
__global__ void zero_cnt(int n)
{
    int i = blockIdx.x * blockDim.x + threadIdx.x;
    if (i < n) g_cnt[i] = 0;
}

__global__ void count_deg(const int* __restrict__ dst, int E)
{
    int e = blockIdx.x * blockDim.x + threadIdx.x;
    if (e < E) atomicAdd(&g_cnt[dst[e]], 1);
}

__global__ __launch_bounds__(256) void scan_blk(int n)
{
    __shared__ int ws[8];
    int b = blockIdx.x, t = threadIdx.x;
    int idx = b * 256 + t;
    int lane = t & 31, wid = t >> 5;
    int v = (idx < n) ? g_cnt[idx] : 0;
    int incl = v;
#pragma unroll
    for (int o = 1; o < 32; o <<= 1) {
        int u = __shfl_up_sync(0xffffffffu, incl, o);
        if (lane >= o) incl += u;
    }
    if (lane == 31) ws[wid] = incl;
    __syncthreads();
    if (t < 8) {
        int a = ws[t];
        int p = a;
#pragma unroll
        for (int o = 1; o < 8; o <<= 1) {
            int u = __shfl_up_sync(0xffu, p, o);
            if (t >= o) p += u;
        }
        ws[t] = p - a;
        if (t == 7) g_bsum[b] = p;
    }
    __syncthreads();
    if (idx < n) g_off[idx] = incl - v + ws[wid];
}

__global__ __launch_bounds__(256) void scan_tot(int nb, int n)
{
    __shared__ int ws[8];
    int t = threadIdx.x;
    int lane = t & 31, wid = t >> 5;
    int v = (t < nb) ? g_bsum[t] : 0;
    int incl = v;
#pragma unroll
    for (int o = 1; o < 32; o <<= 1) {
        int u = __shfl_up_sync(0xffffffffu, incl, o);
        if (lane >= o) incl += u;
    }
    if (lane == 31) ws[wid] = incl;
    __syncthreads();
    if (t < 8) {
        int a = ws[t];
        int p = a;
#pragma unroll
        for (int o = 1; o < 8; o <<= 1) {
            int u = __shfl_up_sync(0xffu, p, o);
            if (t >= o) p += u;
        }
        ws[t] = p - a;
        if (t == 7) g_off[n] = p;
    }
    __syncthreads();
    g_boff[t] = incl - v + ws[wid];
}

__global__ void scan_add(int n)
{
    int b = blockIdx.x, t = threadIdx.x;
    int idx = b * 256 + t;
    if (idx < n) {
        int o = g_off[idx] + g_boff[b];
        g_off[idx] = o;
        g_cur[idx] = o;
    }
}

__global__ void bucket_edges(const int* __restrict__ src, const int* __restrict__ dst, int E)
{
    int e = blockIdx.x * blockDim.x + threadIdx.x;
    if (e >= E) return;
    int p = atomicAdd(&g_cur[dst[e]], 1);
    g_eid[p]  = e;
    g_esrc[p] = src[e];
}

// ------- fused per-node online-softmax aggregation: 64 thr, 2 features/thread -------
__global__ __launch_bounds__(64) void node_aggregate(
    const float* __restrict__ bond, const float* __restrict__ dd,
    const float* __restrict__ attn)
{
    int node = blockIdx.x;
    int t = threadIdx.x;
    int beg = g_off[node], end = g_off[node + 1];

    __nv_bfloat162 q2 = *(const __nv_bfloat162*)(&g_qh[(size_t)node * HIDD + 2 * t]);
    float qx = __bfloat162float(q2.x), qy = __bfloat162float(q2.y);
    float2 av = *(const float2*)(attn + 2 * t);

    float m = __int_as_float(0xff800000);
    float s = 0.f;
    float ax = 0.f, ay = 0.f;

    int i = beg;
    for (; i + 1 < end; i += 2) {
        int e0 = g_eid[i],     s0 = g_esrc[i];
        int e1 = g_eid[i + 1], s1 = g_esrc[i + 1];
        __nv_bfloat162 k0 = *(const __nv_bfloat162*)(&g_kh[(size_t)s0 * HIDD + 2 * t]);
        __nv_bfloat162 k1 = *(const __nv_bfloat162*)(&g_kh[(size_t)s1 * HIDD + 2 * t]);
        float2 b0 = *(const float2*)(bond + (size_t)e0 * HIDD + 2 * t);
        float2 b1 = *(const float2*)(bond + (size_t)e1 * HIDD + 2 * t);
        float dd0 = dd[e0], dd1 = dd[e1];

        float v0x = __bfloat162float(k0.x) + qx;
        float v0y = __bfloat162float(k0.y) + qy;
        float v1x = __bfloat162float(k1.x) + qx;
        float v1y = __bfloat162float(k1.y) + qy;
        v0x = (v0x > 0.f) ? v0x : 0.01f * v0x;
        v0y = (v0y > 0.f) ? v0y : 0.01f * v0y;
        v1x = (v1x > 0.f) ? v1x : 0.01f * v1x;
        v1y = (v1y > 0.f) ? v1y : 0.01f * v1y;
        float p0 = v0x * av.x + v0y * av.y;
        float p1 = v1x * av.x + v1y * av.y;
#pragma unroll
        for (int o = 4; o; o >>= 1) {
            p0 += __shfl_xor_sync(0xffffffffu, p0, o, 8);
            p1 += __shfl_xor_sync(0xffffffffu, p1, o, 8);
        }
        float z0 = p0 + dd0;
        float z1 = p1 + dd1;
        float mn = fmaxf(m, fmaxf(z0, z1));
        float corr = __expf(m - mn);
        float w0 = __expf(z0 - mn);
        float w1 = __expf(z1 - mn);
        ax = ax * corr + w0 * b0.x + w1 * b1.x;
        ay = ay * corr + w0 * b0.y + w1 * b1.y;
        s  = s  * corr + w0 + w1;
        m  = mn;
    }
    if (i < end) {
        int e0 = g_eid[i], s0 = g_esrc[i];
        __nv_bfloat162 k0 = *(const __nv_bfloat162*)(&g_kh[(size_t)s0 * HIDD + 2 * t]);
        float2 b0 = *(const float2*)(bond + (size_t)e0 * HIDD + 2 * t);
        float dd0 = dd[e0];
        float v0x = __bfloat162float(k0.x) + qx;
        float v0y = __bfloat162float(k0.y) + qy;
        v0x = (v0x > 0.f) ? v0x : 0.01f * v0x;
        v0y = (v0y > 0.f) ? v0y : 0.01f * v0y;
        float p0 = v0x * av.x + v0y * av.y;
#pragma unroll
        for (int o = 4; o; o >>= 1) p0 += __shfl_xor_sync(0xffffffffu, p0, o, 8);
        float z0 = p0 + dd0;
        float mn = fmaxf(m, z0);
        float corr = __expf(m - mn);
        float w0 = __expf(z0 - mn);
        ax = ax * corr + w0 * b0.x;
        ay = ay * corr + w0 * b0.y;
        s  = s  * corr + w0;
    }
    float inv = (s > 0.f) ? 1.f / s : 0.f;
    *(float2*)(g_ft + (size_t)node * HIDD + 2 * t) = make_float2(ax * inv, ay * inv);
}

// ---------------- launch ----------------
extern "C" void kernel_launch(void* const* d_in, const int* in_sizes, int n_in,
                              void* d_out, int out_size)
{
    const int*   src  = (const int*)d_in[0];
    const int*   dst  = (const int*)d_in[1];
    const float* bond = (const float*)d_in[2];
    const float* atom = (const float*)d_in[3];
    const float* dd   = (const float*)d_in[4];
    const float* k_w  = (const float*)d_in[5];
    const float* k_b  = (const float*)d_in[6];
    const float* q_w  = (const float*)d_in[7];
    const float* q_b  = (const float*)d_in[8];
    const float* attn = (const float*)d_in[9];
    const float* l1w  = (const float*)d_in[10];
    const float* l1b  = (const float*)d_in[11];
    const float* l2w  = (const float*)d_in[12];
    const float* l2b  = (const float*)d_in[13];
    const float* r1aw = (const float*)d_in[14];
    const float* r1ab = (const float*)d_in[15];
    const float* r1bw = (const float*)d_in[16];
    const float* r1bb = (const float*)d_in[17];
    const float* r2aw = (const float*)d_in[18];
    const float* r2ab = (const float*)d_in[19];
    const float* r2bw = (const float*)d_in[20];
    const float* r2bb = (const float*)d_in[21];
    float* out = (float*)d_out;

    int E = in_sizes[0];
    int n = in_sizes[3] / HIDD;

    float* ftbuf;
    cudaGetSymbolAddress((void**)&ftbuf, g_ft);

    cudaFuncSetAttribute(proj_kq, cudaFuncAttributeMaxDynamicSharedMemorySize, SMEM_GEMM);
    cudaFuncSetAttribute(mlp6, cudaFuncAttributeMaxDynamicSharedMemorySize, SMEM_GEMM);

    int nb = (n + 255) / 256;
    int gblocks = (n + 63) / 64;

    zero_cnt<<<nb, 256>>>(n);
    count_deg<<<(E + 255) / 256, 256>>>(dst, E);
    wprep<<<8, 256>>>(k_w, q_w, l1w, l2w, r1aw, r1bw, r2aw, r2bw);
    proj_kq<<<gblocks, NT, SMEM_GEMM>>>(atom, k_b, q_b, n);
    scan_blk<<<nb, 256>>>(n);
    scan_tot<<<1, 256>>>(nb, n);
    scan_add<<<nb, 256>>>(n);
    bucket_edges<<<(E + 255) / 256, 256>>>(src, dst, E);

    node_aggregate<<<n, 64>>>(bond, dd, attn);

    mlp6<<<gblocks, NT, SMEM_GEMM>>>(ftbuf, atom,
                                     l1b, l2b, r1ab, r1bb, r2ab, r2bb,
                                     out, n);
}

// round 17
// speedup vs baseline: 1.0437x; 1.0437x over previous
#include <cuda_runtime.h>
#include <cuda_bf16.h>
#include <cstdint>

#define NN   50000
#define EE   640000
#define HIDD 128
#define NT   256   // 8 warps per GEMM CTA, 2 CTAs/SM

// ---------------- device scratch ----------------
__device__ float         g_ft[NN * HIDD];
__device__ __nv_bfloat16 g_kh[NN * HIDD];
__device__ __nv_bfloat16 g_qh[NN * HIDD];
__device__ float4        g_wbf[8 * 4096];   // 8 matrices x (32KB hi + 32KB lo), swizzled
__device__ int   g_cnt[NN];
__device__ int   g_off[NN + 1];
__device__ int   g_cur[NN];
__device__ int   g_eid[EE];
__device__ int   g_esrc[EE];
__device__ int   g_bsum[256];
__device__ int   g_boff[256];

// ---------------- warp-mma helpers ----------------
__device__ __forceinline__ uint32_t smem_u32(const void* p)
{
    uint32_t a;
    asm("{ .reg .u64 t; cvta.to.shared.u64 t, %1; cvt.u32.u64 %0, t; }" : "=r"(a) : "l"(p));
    return a;
}
__device__ __forceinline__ void ldsm4(uint32_t& r0, uint32_t& r1, uint32_t& r2, uint32_t& r3,
                                      uint32_t addr)
{
    asm volatile("ldmatrix.sync.aligned.m8n8.x4.shared.b16 {%0,%1,%2,%3}, [%4];"
                 : "=r"(r0), "=r"(r1), "=r"(r2), "=r"(r3) : "r"(addr));
}
__device__ __forceinline__ void mma16816(float* c, const uint32_t* a, uint32_t b0, uint32_t b1)
{
    asm volatile(
        "mma.sync.aligned.m16n8k16.row.col.f32.bf16.bf16.f32 "
        "{%0,%1,%2,%3}, {%4,%5,%6,%7}, {%8,%9}, {%0,%1,%2,%3};"
        : "+f"(c[0]), "+f"(c[1]), "+f"(c[2]), "+f"(c[3])
        : "r"(a[0]), "r"(a[1]), "r"(a[2]), "r"(a[3]), "r"(b0), "r"(b1));
}

#define CP_COMMIT() asm volatile("cp.async.commit_group;" ::: "memory")
#define CP_WAIT(n)  asm volatile("cp.async.wait_group %0;" :: "n"(n) : "memory")

__device__ __forceinline__ uint32_t sw(int r, int u)
{
    return (uint32_t)(r * 256 + ((u ^ (r & 7)) << 4));
}

// SMEM: X hi/lo (64 rows, 32KB) + two 32KB W half-buffers = 96KB -> 2 CTAs/SM
#define XH_OFF  0
#define XL_OFF  16384
#define WA_OFF  32768
#define WB_OFF  65536
#define SMEM_GEMM 98304

__device__ __forceinline__ void split_store(char* base, int hi_off, int lo_off,
                                            int r, int u, const float* f)
{
    __nv_bfloat162 hi[4], lo[4];
#pragma unroll
    for (int p = 0; p < 4; p++) {
        __nv_bfloat16 h0 = __float2bfloat16(f[p * 2]);
        __nv_bfloat16 h1 = __float2bfloat16(f[p * 2 + 1]);
        hi[p] = __nv_bfloat162(h0, h1);
        lo[p] = __nv_bfloat162(__float2bfloat16(f[p * 2] - __bfloat162float(h0)),
                               __float2bfloat16(f[p * 2 + 1] - __bfloat162float(h1)));
    }
    uint32_t o = sw(r, u);
    *(uint4*)(base + hi_off + o) = *(uint4*)hi;
    *(uint4*)(base + lo_off + o) = *(uint4*)lo;
}

// stage 64 rows of X
__device__ __forceinline__ void stage_X(char* smem, const float* src, int row0, int n, int tid)
{
#pragma unroll
    for (int j = 0; j < 4; j++) {
        int i = tid + NT * j;
        int r = i >> 4, u = i & 15;
        int gr = row0 + r;
        float4 f0 = make_float4(0.f, 0.f, 0.f, 0.f), f1 = f0;
        if (gr < n) {
            f0 = ((const float4*)(src + (size_t)gr * HIDD))[u * 2];
            f1 = ((const float4*)(src + (size_t)gr * HIDD))[u * 2 + 1];
        }
        float f[8] = {f0.x, f0.y, f0.z, f0.w, f1.x, f1.y, f1.z, f1.w};
        split_store(smem, XH_OFF, XL_OFF, r, u, f);
    }
}

// async copy of a 32KB weight half-block into a smem half-buffer
__device__ __forceinline__ void cpasync_W32(uint32_t sb_dst, const char* gsrc, int tid)
{
#pragma unroll
    for (int j = 0; j < 8; j++) {
        int i = tid + NT * j;
        asm volatile("cp.async.cg.shared.global [%0], [%1], 16;"
                     :: "r"(sb_dst + i * 16), "l"(gsrc + (size_t)i * 16) : "memory");
    }
}

// passes 0+1: acc = Xh*Wh + Xl*Wh  (zeroes acc)
__device__ __forceinline__ void mma_pass01(uint32_t sb, uint32_t woff,
                                           int wid, int lane, float acc[8][4])
{
    int m0 = (wid >> 1) * 16;
    int n0 = (wid & 1) * 64;
    int sel = lane >> 3, lr = lane & 7;
    int us = sel >> 1;
    int ra = (sel & 1) * 8 + lr;

#pragma unroll
    for (int a = 0; a < 8; a++)
#pragma unroll
        for (int p = 0; p < 4; p++) acc[a][p] = 0.f;

    int arow = m0 + ra;
    int brow[4];
#pragma unroll
    for (int j = 0; j < 4; j++) brow[j] = n0 + j * 16 + ra;

#pragma unroll
    for (int k = 0; k < 8; k++) {
        int u = 2 * k + us;
        uint32_t ah[4], al[4], bb[4][4];
        {
            uint32_t o = sw(arow, u);
            ldsm4(ah[0], ah[1], ah[2], ah[3], sb + XH_OFF + o);
            ldsm4(al[0], al[1], al[2], al[3], sb + XL_OFF + o);
        }
#pragma unroll
        for (int j = 0; j < 4; j++) {
            uint32_t o = sw(brow[j], u);
            ldsm4(bb[j][0], bb[j][1], bb[j][2], bb[j][3], sb + woff + o);
        }
#pragma unroll
        for (int j = 0; j < 4; j++)
#pragma unroll
            for (int p = 0; p < 2; p++)
                mma16816(acc[2 * j + p], ah, bb[j][p], bb[j][p + 2]);
#pragma unroll
        for (int j = 0; j < 4; j++)
#pragma unroll
            for (int p = 0; p < 2; p++)
                mma16816(acc[2 * j + p], al, bb[j][p], bb[j][p + 2]);
    }
}

// pass 2: acc += Xh*Wl
__device__ __forceinline__ void mma_pass2(uint32_t sb, uint32_t woff,
                                          int wid, int lane, float acc[8][4])
{
    int m0 = (wid >> 1) * 16;
    int n0 = (wid & 1) * 64;
    int sel = lane >> 3, lr = lane & 7;
    int us = sel >> 1;
    int ra = (sel & 1) * 8 + lr;

    int arow = m0 + ra;
    int brow[4];
#pragma unroll
    for (int j = 0; j < 4; j++) brow[j] = n0 + j * 16 + ra;

#pragma unroll
    for (int k = 0; k < 8; k++) {
        int u = 2 * k + us;
        uint32_t ah[4], bb[4][4];
        {
            uint32_t o = sw(arow, u);
            ldsm4(ah[0], ah[1], ah[2], ah[3], sb + XH_OFF + o);
        }
#pragma unroll
        for (int j = 0; j < 4; j++) {
            uint32_t o = sw(brow[j], u);
            ldsm4(bb[j][0], bb[j][1], bb[j][2], bb[j][3], sb + woff + o);
        }
#pragma unroll
        for (int j = 0; j < 4; j++)
#pragma unroll
            for (int p = 0; p < 2; p++)
                mma16816(acc[2 * j + p], ah, bb[j][p], bb[j][p + 2]);
    }
}

// =============== weight pre-conversion: fp32 -> swizzled bf16 hi/lo ===============
__global__ __launch_bounds__(256) void wprep(
    const float* w0, const float* w1, const float* w2, const float* w3,
    const float* w4, const float* w5, const float* w6, const float* w7)
{
    const float* W;
    switch (blockIdx.x) {
        case 0: W = w0; break; case 1: W = w1; break;
        case 2: W = w2; break; case 3: W = w3; break;
        case 4: W = w4; break; case 5: W = w5; break;
        case 6: W = w6; break; default: W = w7; break;
    }
    char* dst = (char*)g_wbf + (size_t)blockIdx.x * 65536;
    int tid = threadIdx.x;
#pragma unroll
    for (int j = 0; j < 8; j++) {
        int i = tid + 256 * j;
        int r = i >> 4, u = i & 15;
        float4 f0 = ((const float4*)(W + (size_t)r * HIDD))[u * 2];
        float4 f1 = ((const float4*)(W + (size_t)r * HIDD))[u * 2 + 1];
        float f[8] = {f0.x, f0.y, f0.z, f0.w, f1.x, f1.y, f1.z, f1.w};
        split_store(dst, 0, 32768, r, u, f);
    }
}

// =============== fused k+q projection -> bf16 K/Q (split-K pipelined W) ===============
__global__ __launch_bounds__(NT, 2) void proj_kq(
    const float* __restrict__ atom,
    const float* __restrict__ k_b, const float* __restrict__ q_b, int n)
{
    extern __shared__ char smem[];
    uint32_t sb = smem_u32(smem);
    int tid = threadIdx.x, wid = tid >> 5, lane = tid & 31;
    int row0 = blockIdx.x * 64;
    int m0 = (wid >> 1) * 16;
    int n0 = (wid & 1) * 64;

    const char* gw = (const char*)g_wbf;
    cpasync_W32(sb + WA_OFF, gw, tid);          CP_COMMIT();   // WHk -> A
    cpasync_W32(sb + WB_OFF, gw + 32768, tid);  CP_COMMIT();   // WLk -> B
    stage_X(smem, atom, row0, n, tid);

    float acc[8][4];

    // ---- k ----
    CP_WAIT(1); __syncthreads();
    mma_pass01(sb, WA_OFF, wid, lane, acc);
    __syncthreads();
    cpasync_W32(sb + WA_OFF, gw + 65536, tid); CP_COMMIT();   // WHq -> A
    CP_WAIT(1); __syncthreads();
    mma_pass2(sb, WB_OFF, wid, lane, acc);
    __syncthreads();
    cpasync_W32(sb + WB_OFF, gw + 65536 + 32768, tid); CP_COMMIT();   // WLq -> B
    {
        int rbase = row0 + m0 + (lane >> 2);
#pragma unroll
        for (int a = 0; a < 8; a++) {
            int col = n0 + a * 8 + (lane & 3) * 2;
            float2 bv = *(const float2*)(k_b + col);
#pragma unroll
            for (int h = 0; h < 2; h++) {
                int row = rbase + h * 8;
                if (row >= n) continue;
                *(__nv_bfloat162*)(&g_kh[(size_t)row * HIDD + col]) =
                    __nv_bfloat162(__float2bfloat16(acc[a][h * 2] + bv.x),
                                   __float2bfloat16(acc[a][h * 2 + 1] + bv.y));
            }
        }
    }
    // ---- q ----
    CP_WAIT(1); __syncthreads();
    mma_pass01(sb, WA_OFF, wid, lane, acc);
    CP_WAIT(0); __syncthreads();
    mma_pass2(sb, WB_OFF, wid, lane, acc);
    {
        int rbase = row0 + m0 + (lane >> 2);
#pragma unroll
        for (int a = 0; a < 8; a++) {
            int col = n0 + a * 8 + (lane & 3) * 2;
            float2 bv = *(const float2*)(q_b + col);
#pragma unroll
            for (int h = 0; h < 2; h++) {
                int row = rbase + h * 8;
                if (row >= n) continue;
                *(__nv_bfloat162*)(&g_qh[(size_t)row * HIDD + col]) =
                    __nv_bfloat162(__float2bfloat16(acc[a][h * 2] + bv.x),
                                   __float2bfloat16(acc[a][h * 2 + 1] + bv.y));
            }
        }
    }
}

// =============== fused 6-layer MLP: split-K pipelined W, reg carry ===============
__global__ __launch_bounds__(NT, 2) void mlp6(
    const float* __restrict__ FT, const float* __restrict__ atom,
    const float* __restrict__ l1b, const float* __restrict__ l2b,
    const float* __restrict__ r1ab, const float* __restrict__ r1bb,
    const float* __restrict__ r2ab, const float* __restrict__ r2bb,
    float* __restrict__ out, int n)
{
    extern __shared__ char smem[];
    uint32_t sb = smem_u32(smem);
    int tid = threadIdx.x, wid = tid >> 5, lane = tid & 31;
    int row0 = blockIdx.x * 64;
    int m0 = (wid >> 1) * 16;
    int n0 = (wid & 1) * 64;

    const float* Bs[6] = {l1b, l2b, r1ab, r1bb, r2ab, r2bb};
    const int reluF[6] = {1, 0, 1, 1, 1, 1};
    const int resF[6]  = {0, 1, 0, 2, 0, 2};   // 0 none, 1 atom, 2 reg-carry
    const int outF[6]  = {0, 1, 0, 1, 0, 2};   // 0 X, 1 X + save carry, 2 out

    const char* gw = (const char*)g_wbf;
    cpasync_W32(sb + WA_OFF, gw + (size_t)2 * 65536, tid);         CP_COMMIT();
    cpasync_W32(sb + WB_OFF, gw + (size_t)2 * 65536 + 32768, tid); CP_COMMIT();
    stage_X(smem, FT, row0, n, tid);

    float acc[8][4];
    float car[8][4];

#pragma unroll
    for (int L = 0; L < 6; L++) {
        CP_WAIT(1); __syncthreads();
        mma_pass01(sb, WA_OFF, wid, lane, acc);
        __syncthreads();
        if (L < 5) {
            cpasync_W32(sb + WA_OFF, gw + (size_t)(3 + L) * 65536, tid);
            CP_COMMIT();
        }
        if (L < 5) { CP_WAIT(1); } else { CP_WAIT(0); }
        __syncthreads();
        mma_pass2(sb, WB_OFF, wid, lane, acc);

        int rbase = row0 + m0 + (lane >> 2);
#pragma unroll
        for (int a = 0; a < 8; a++) {
            int col = n0 + a * 8 + (lane & 3) * 2;
            float2 bv = *(const float2*)(Bs[L] + col);
#pragma unroll
            for (int h = 0; h < 2; h++) {
                int row = rbase + h * 8;
                float vx = acc[a][h * 2]     + bv.x;
                float vy = acc[a][h * 2 + 1] + bv.y;
                if (reluF[L]) { vx = fmaxf(vx, 0.f); vy = fmaxf(vy, 0.f); }
                if (resF[L] == 1) {
                    if (row < n) {
                        float2 rv = *(const float2*)(atom + (size_t)row * HIDD + col);
                        vx += rv.x; vy += rv.y;
                    }
                } else if (resF[L] == 2) {
                    vx += car[a][h * 2];
                    vy += car[a][h * 2 + 1];
                }
                acc[a][h * 2]     = vx;
                acc[a][h * 2 + 1] = vy;
                if (outF[L] == 1) {
                    car[a][h * 2]     = vx;
                    car[a][h * 2 + 1] = vy;
                }
            }
        }
        __syncthreads();

        if (L < 5) {
            cpasync_W32(sb + WB_OFF, gw + (size_t)(3 + L) * 65536 + 32768, tid);
            CP_COMMIT();
        }

        int rl0 = m0 + (lane >> 2);
#pragma unroll
        for (int a = 0; a < 8; a++) {
            int col = n0 + a * 8 + (lane & 3) * 2;
            int u = col >> 3;
#pragma unroll
            for (int h = 0; h < 2; h++) {
                int lr = rl0 + h * 8;
                float vx = acc[a][h * 2], vy = acc[a][h * 2 + 1];
                if (outF[L] == 2) {
                    int row = row0 + lr;
                    if (row < n)
                        *(float2*)(out + (size_t)row * HIDD + col) = make_float2(vx, vy);
                } else {
                    __nv_bfloat16 hx = __float2bfloat16(vx);
                    __nv_bfloat16 hy = __float2bfloat16(vy);
                    uint32_t o = sw(lr, u) + ((col & 7) << 1);
                    *(__nv_bfloat162*)(smem + XH_OFF + o) = __nv_bfloat162(hx, hy);
                    *(__nv_bfloat162*)(smem + XL_OFF + o) =
                        __nv_bfloat162(__float2bfloat16(vx - __bfloat162float(hx)),
                                       __float2bfloat16(vy - __bfloat162float(hy)));
                }
            }
        }
    }
}

// ---------------- CSR build ----------------
__global__ void zero_cnt(int n)
{
    int i = blockIdx.x * blockDim.x + threadIdx.x;
    if (i < n) g_cnt[i] = 0;
}

__global__ void count_deg(const int* __restrict__ dst, int E)
{
    int e = blockIdx.x * blockDim.x + threadIdx.x;
    if (e < E) atomicAdd(&g_cnt[dst[e]], 1);
}

__global__ __launch_bounds__(256) void scan_blk(int n)
{
    __shared__ int ws[8];
    int b = blockIdx.x, t = threadIdx.x;
    int idx = b * 256 + t;
    int lane = t & 31, wid = t >> 5;
    int v = (idx < n) ? g_cnt[idx] : 0;
    int incl = v;
#pragma unroll
    for (int o = 1; o < 32; o <<= 1) {
        int u = __shfl_up_sync(0xffffffffu, incl, o);
        if (lane >= o) incl += u;
    }
    if (lane == 31) ws[wid] = incl;
    __syncthreads();
    if (t < 8) {
        int a = ws[t];
        int p = a;
#pragma unroll
        for (int o = 1; o < 8; o <<= 1) {
            int u = __shfl_up_sync(0xffu, p, o);
            if (t >= o) p += u;
        }
        ws[t] = p - a;
        if (t == 7) g_bsum[b] = p;
    }
    __syncthreads();
    if (idx < n) g_off[idx] = incl - v + ws[wid];
}

__global__ __launch_bounds__(256) void scan_tot(int nb, int n)
{
    __shared__ int ws[8];
    int t = threadIdx.x;
    int lane = t & 31, wid = t >> 5;
    int v = (t < nb) ? g_bsum[t] : 0;
    int incl = v;
#pragma unroll
    for (int o = 1; o < 32; o <<= 1) {
        int u = __shfl_up_sync(0xffffffffu, incl, o);
        if (lane >= o) incl += u;
    }
    if (lane == 31) ws[wid] = incl;
    __syncthreads();
    if (t < 8) {
        int a = ws[t];
        int p = a;
#pragma unroll
        for (int o = 1; o < 8; o <<= 1) {
            int u = __shfl_up_sync(0xffu, p, o);
            if (t >= o) p += u;
        }
        ws[t] = p - a;
        if (t == 7) g_off[n] = p;
    }
    __syncthreads();
    g_boff[t] = incl - v + ws[wid];
}

__global__ void scan_add(int n)
{
    int b = blockIdx.x, t = threadIdx.x;
    int idx = b * 256 + t;
    if (idx < n) {
        int o = g_off[idx] + g_boff[b];
        g_off[idx] = o;
        g_cur[idx] = o;
    }
}

__global__ void bucket_edges(const int* __restrict__ src, const int* __restrict__ dst, int E)
{
    int e = blockIdx.x * blockDim.x + threadIdx.x;
    if (e >= E) return;
    int p = atomicAdd(&g_cur[dst[e]], 1);
    g_eid[p]  = e;
    g_esrc[p] = src[e];
}

// ------- fused per-node online-softmax aggregation: 64 thr, 2 features/thread -------
__global__ __launch_bounds__(64) void node_aggregate(
    const float* __restrict__ bond, const float* __restrict__ dd,
    const float* __restrict__ attn)
{
    int node = blockIdx.x;
    int t = threadIdx.x;
    int beg = g_off[node], end = g_off[node + 1];

    __nv_bfloat162 q2 = *(const __nv_bfloat162*)(&g_qh[(size_t)node * HIDD + 2 * t]);
    float qx = __bfloat162float(q2.x), qy = __bfloat162float(q2.y);
    float2 av = *(const float2*)(attn + 2 * t);

    float m = __int_as_float(0xff800000);
    float s = 0.f;
    float ax = 0.f, ay = 0.f;

    int i = beg;
    for (; i + 1 < end; i += 2) {
        int e0 = g_eid[i],     s0 = g_esrc[i];
        int e1 = g_eid[i + 1], s1 = g_esrc[i + 1];
        __nv_bfloat162 k0 = *(const __nv_bfloat162*)(&g_kh[(size_t)s0 * HIDD + 2 * t]);
        __nv_bfloat162 k1 = *(const __nv_bfloat162*)(&g_kh[(size_t)s1 * HIDD + 2 * t]);
        float2 b0 = *(const float2*)(bond + (size_t)e0 * HIDD + 2 * t);
        float2 b1 = *(const float2*)(bond + (size_t)e1 * HIDD + 2 * t);
        float dd0 = dd[e0], dd1 = dd[e1];

        float v0x = __bfloat162float(k0.x) + qx;
        float v0y = __bfloat162float(k0.y) + qy;
        float v1x = __bfloat162float(k1.x) + qx;
        float v1y = __bfloat162float(k1.y) + qy;
        v0x = (v0x > 0.f) ? v0x : 0.01f * v0x;
        v0y = (v0y > 0.f) ? v0y : 0.01f * v0y;
        v1x = (v1x > 0.f) ? v1x : 0.01f * v1x;
        v1y = (v1y > 0.f) ? v1y : 0.01f * v1y;
        float p0 = v0x * av.x + v0y * av.y;
        float p1 = v1x * av.x + v1y * av.y;
#pragma unroll
        for (int o = 4; o; o >>= 1) {
            p0 += __shfl_xor_sync(0xffffffffu, p0, o, 8);
            p1 += __shfl_xor_sync(0xffffffffu, p1, o, 8);
        }
        float z0 = p0 + dd0;
        float z1 = p1 + dd1;
        float mn = fmaxf(m, fmaxf(z0, z1));
        float corr = __expf(m - mn);
        float w0 = __expf(z0 - mn);
        float w1 = __expf(z1 - mn);
        ax = ax * corr + w0 * b0.x + w1 * b1.x;
        ay = ay * corr + w0 * b0.y + w1 * b1.y;
        s  = s  * corr + w0 + w1;
        m  = mn;
    }
    if (i < end) {
        int e0 = g_eid[i], s0 = g_esrc[i];
        __nv_bfloat162 k0 = *(const __nv_bfloat162*)(&g_kh[(size_t)s0 * HIDD + 2 * t]);
        float2 b0 = *(const float2*)(bond + (size_t)e0 * HIDD + 2 * t);
        float dd0 = dd[e0];
        float v0x = __bfloat162float(k0.x) + qx;
        float v0y = __bfloat162float(k0.y) + qy;
        v0x = (v0x > 0.f) ? v0x : 0.01f * v0x;
        v0y = (v0y > 0.f) ? v0y : 0.01f * v0y;
        float p0 = v0x * av.x + v0y * av.y;
#pragma unroll
        for (int o = 4; o; o >>= 1) p0 += __shfl_xor_sync(0xffffffffu, p0, o, 8);
        float z0 = p0 + dd0;
        float mn = fmaxf(m, z0);
        float corr = __expf(m - mn);
        float w0 = __expf(z0 - mn);
        ax = ax * corr + w0 * b0.x;
        ay = ay * corr + w0 * b0.y;
        s  = s  * corr + w0;
    }
    float inv = (s > 0.f) ? 1.f / s : 0.f;
    *(float2*)(g_ft + (size_t)node * HIDD + 2 * t) = make_float2(ax * inv, ay * inv);
}

// ---------------- launch ----------------
extern "C" void kernel_launch(void* const* d_in, const int* in_sizes, int n_in,
                              void* d_out, int out_size)
{
    const int*   src  = (const int*)d_in[0];
    const int*   dst  = (const int*)d_in[1];
    const float* bond = (const float*)d_in[2];
    const float* atom = (const float*)d_in[3];
    const float* dd   = (const float*)d_in[4];
    const float* k_w  = (const float*)d_in[5];
    const float* k_b  = (const float*)d_in[6];
    const float* q_w  = (const float*)d_in[7];
    const float* q_b  = (const float*)d_in[8];
    const float* attn = (const float*)d_in[9];
    const float* l1w  = (const float*)d_in[10];
    const float* l1b  = (const float*)d_in[11];
    const float* l2w  = (const float*)d_in[12];
    const float* l2b  = (const float*)d_in[13];
    const float* r1aw = (const float*)d_in[14];
    const float* r1ab = (const float*)d_in[15];
    const float* r1bw = (const float*)d_in[16];
    const float* r1bb = (const float*)d_in[17];
    const float* r2aw = (const float*)d_in[18];
    const float* r2ab = (const float*)d_in[19];
    const float* r2bw = (const float*)d_in[20];
    const float* r2bb = (const float*)d_in[21];
    float* out = (float*)d_out;

    int E = in_sizes[0];
    int n = in_sizes[3] / HIDD;

    float* ftbuf;
    cudaGetSymbolAddress((void**)&ftbuf, g_ft);

    cudaFuncSetAttribute(proj_kq, cudaFuncAttributeMaxDynamicSharedMemorySize, SMEM_GEMM);
    cudaFuncSetAttribute(mlp6, cudaFuncAttributeMaxDynamicSharedMemorySize, SMEM_GEMM);

    int nb = (n + 255) / 256;
    int gblocks = (n + 63) / 64;

    // fork a side stream for the CSR chain, overlapping wprep + proj_kq
    cudaStream_t s2;
    cudaEvent_t evFork, evJoin;
    cudaStreamCreateWithFlags(&s2, cudaStreamNonBlocking);
    cudaEventCreateWithFlags(&evFork, cudaEventDisableTiming);
    cudaEventCreateWithFlags(&evJoin, cudaEventDisableTiming);

    cudaEventRecord(evFork, 0);             // fork point on main (legacy) stream
    cudaStreamWaitEvent(s2, evFork, 0);

    // side stream: CSR build
    zero_cnt<<<nb, 256, 0, s2>>>(n);
    count_deg<<<(E + 255) / 256, 256, 0, s2>>>(dst, E);
    scan_blk<<<nb, 256, 0, s2>>>(n);
    scan_tot<<<1, 256, 0, s2>>>(nb, n);
    scan_add<<<nb, 256, 0, s2>>>(n);
    bucket_edges<<<(E + 255) / 256, 256, 0, s2>>>(src, dst, E);
    cudaEventRecord(evJoin, s2);

    // main stream: weights + projections
    wprep<<<8, 256>>>(k_w, q_w, l1w, l2w, r1aw, r1bw, r2aw, r2bw);
    proj_kq<<<gblocks, NT, SMEM_GEMM>>>(atom, k_b, q_b, n);

    cudaStreamWaitEvent(0, evJoin, 0);      // join before aggregation

    node_aggregate<<<n, 64>>>(bond, dd, attn);

    mlp6<<<gblocks, NT, SMEM_GEMM>>>(ftbuf, atom,
                                     l1b, l2b, r1ab, r1bb, r2ab, r2bb,
                                     out, n);

    cudaEventDestroy(evFork);
    cudaEventDestroy(evJoin);
    cudaStreamDestroy(s2);
}